// round 4
// baseline (speedup 1.0000x reference)
#include <cuda_runtime.h>
#include <cstdint>

#define DIMS 64
#define SVOL (64*64*64)
#define NBATCH 4
#define NCLASS 4
#define NPAIR 12
#define NVOL 24
#define NTOT (NBATCH*SVOL)
#define INF_SENT 1e12f
#define SMOOTHV 1e-5f

typedef unsigned long long u64b;

__device__ float g_F [(size_t)NVOL * SVOL];
__device__ float g_F2[(size_t)NVOL * SVOL];
__device__ float g_prob[(size_t)NPAIR * SVOL];
__device__ float g_TP[16];
__device__ float g_PS[16];
__device__ float g_CNT[16];
__device__ float g_focal;
__device__ float g_bsum[NPAIR];
__device__ int   g_flag64;

__device__ __forceinline__ void cp_async16(uint32_t dst, const float* src) {
    asm volatile("cp.async.cg.shared.global [%0], [%1], 16;" :: "r"(dst), "l"(src));
}
__device__ __forceinline__ u64b pack2(float lo, float hi) {
    u64b r; asm("mov.b64 %0, {%1, %2};" : "=l"(r) : "f"(lo), "f"(hi)); return r;
}
__device__ __forceinline__ u64b fma2(u64b a, u64b b, u64b c) {
    u64b d; asm("fma.rn.f32x2 %0, %1, %2, %3;" : "=l"(d) : "l"(a), "l"(b), "l"(c)); return d;
}
__device__ __forceinline__ u64b add2(u64b a, u64b b) {
    u64b d; asm("add.rn.f32x2 %0, %1, %2;" : "=l"(d) : "l"(a), "l"(b)); return d;
}
__device__ __forceinline__ float f2lo(u64b v) { return __uint_as_float((unsigned)v); }
__device__ __forceinline__ float f2hi(u64b v) { return __uint_as_float((unsigned)(v >> 32)); }

// ============================================================
// K0
// ============================================================
__global__ void k0_init(const int* __restrict__ tgt32) {
    int t = threadIdx.x;
    __shared__ int any;
    if (t == 0) any = 0;
    __syncthreads();
    int v = tgt32[2 * t + 1];
    if (v != 0) atomicOr(&any, 1);
    __syncthreads();
    if (t == 0) g_flag64 = (any == 0) ? 1 : 0;
    if (t < 16) { g_TP[t] = 0.f; g_PS[t] = 0.f; g_CNT[t] = 0.f; }
    if (t < NPAIR) g_bsum[t] = 0.f;
    if (t == 0) g_focal = 0.f;
}

__device__ __forceinline__ float nd2(unsigned long long M, int i) {
    if (M == 0ULL) return INF_SENT;
    unsigned long long L = M << (63 - i);
    int dl = L ? __clzll((long long)L) : 9999;
    unsigned long long R = M >> i;
    int dr = R ? (__ffsll((long long)R) - 1) : 9999;
    int d = min(dl, dr);
    return (float)(d * d);
}

// ============================================================
// K1: softmax, focal, Tversky partials, prob store, EDT pass-1 (W)
// ============================================================
__global__ void __launch_bounds__(256) k1_main(const float* __restrict__ preds,
                                               const int* __restrict__ tgt32) {
    const int tid = threadIdx.x;
    const int g = blockIdx.x * 256 + tid;
    const int b = g >> 18;
    const int s = g & (SVOL - 1);

    const int f64 = g_flag64;
    const int t = tgt32[f64 ? (g << 1) : g];

    const float x0 = preds[(size_t)(b * 4 + 0) * SVOL + s];
    const float x1 = preds[(size_t)(b * 4 + 1) * SVOL + s];
    const float x2 = preds[(size_t)(b * 4 + 2) * SVOL + s];
    const float x3 = preds[(size_t)(b * 4 + 3) * SVOL + s];

    const float m  = fmaxf(fmaxf(x0, x1), fmaxf(x2, x3));
    const float e0 = expf(x0 - m), e1 = expf(x1 - m);
    const float e2 = expf(x2 - m), e3 = expf(x3 - m);
    const float se = e0 + e1 + e2 + e3;
    const float inv = 1.0f / se;
    const float p0 = e0 * inv, p1 = e1 * inv, p2 = e2 * inv, p3 = e3 * inv;

    const float xt = (t == 0) ? x0 : (t == 1) ? x1 : (t == 2) ? x2 : x3;
    const float ce = -(xt - m - logf(se));
    const float pt = (t == 0) ? p0 : (t == 1) ? p1 : (t == 2) ? p2 : p3;
    const float om = 1.0f - pt;
    const float focal = om * om * ce;

    g_prob[(size_t)(b * 3 + 0) * SVOL + s] = p1;
    g_prob[(size_t)(b * 3 + 1) * SVOL + s] = p2;
    g_prob[(size_t)(b * 3 + 2) * SVOL + s] = p3;

    const unsigned full = 0xFFFFFFFFu;
    const unsigned bal1 = __ballot_sync(full, t == 1);
    const unsigned bal2 = __ballot_sync(full, t == 2);
    const unsigned bal3 = __ballot_sync(full, t == 3);
    __shared__ unsigned sb[3][8];
    const int wid = tid >> 5;
    if ((tid & 31) == 0) { sb[0][wid] = bal1; sb[1][wid] = bal2; sb[2][wid] = bal3; }
    __syncthreads();

    const int line = tid >> 6;
    const int i = tid & 63;
#pragma unroll
    for (int cm = 0; cm < 3; cm++) {
        unsigned long long M = (unsigned long long)sb[cm][line * 2] |
                               ((unsigned long long)sb[cm][line * 2 + 1] << 32);
        const int v = (b * 3 + cm) * 2;
        g_F[(size_t)v * SVOL + s]       = nd2(M, i);
        g_F[(size_t)(v + 1) * SVOL + s] = nd2(~M, i);
    }

    float vals[13];
    vals[0] = (t == 0) ? p0 : 0.f;
    vals[1] = (t == 1) ? p1 : 0.f;
    vals[2] = (t == 2) ? p2 : 0.f;
    vals[3] = (t == 3) ? p3 : 0.f;
    vals[4] = p0; vals[5] = p1; vals[6] = p2; vals[7] = p3;
    vals[8]  = (t == 0) ? 1.f : 0.f;
    vals[9]  = (t == 1) ? 1.f : 0.f;
    vals[10] = (t == 2) ? 1.f : 0.f;
    vals[11] = (t == 3) ? 1.f : 0.f;
    vals[12] = focal;

    __shared__ float red[13 * 8];
#pragma unroll
    for (int q = 0; q < 13; q++) {
        float v = vals[q];
#pragma unroll
        for (int o = 16; o > 0; o >>= 1) v += __shfl_down_sync(full, v, o);
        if ((tid & 31) == 0) red[q * 8 + wid] = v;
    }
    __syncthreads();
    if (tid < 13) {
        float sum = 0.f;
#pragma unroll
        for (int k = 0; k < 8; k++) sum += red[tid * 8 + k];
        if (tid < 4)       atomicAdd(&g_TP[b * 4 + tid], sum);
        else if (tid < 8)  atomicAdd(&g_PS[b * 4 + tid - 4], sum);
        else if (tid < 12) atomicAdd(&g_CNT[b * 4 + tid - 8], sum);
        else               atomicAdd(&g_focal, sum);
    }
}

// ============================================================
// K2: EDT pass along H (g_F -> g_F2). Transposed padded tile,
// packed f32x2 over j-pairs. 512 threads, 1 block/slice.
// ============================================================
__global__ void __launch_bounds__(512, 2) k2_passH() {
    __shared__ __align__(16) float T[64 * 66];
    const int v = blockIdx.x >> 6;
    const int d = blockIdx.x & 63;
    const size_t base = (size_t)v * SVOL + (size_t)d * 4096;
    const int tid = threadIdx.x;

    // load slice, fold +h^2, store TRANSPOSED: T[w*66 + h]
    const float4* src = reinterpret_cast<const float4*>(g_F + base);
#pragma unroll
    for (int r = 0; r < 2; r++) {
        int m = tid + r * 512;
        int h = m >> 4;
        int w0 = (m & 15) * 4;
        float4 val = src[m];
        float jv = (float)h, j2 = jv * jv;
        T[(w0 + 0) * 66 + h] = val.x + j2;
        T[(w0 + 1) * 66 + h] = val.y + j2;
        T[(w0 + 2) * 66 + h] = val.z + j2;
        T[(w0 + 3) * 66 + h] = val.w + j2;
    }
    __syncthreads();

    const int w = tid & 63;
    const int gq = tid >> 6;            // rows i = gq + 8k
    float acc[8]; u64b ck2[8];
#pragma unroll
    for (int k = 0; k < 8; k++) {
        acc[k] = 3.0e38f;
        float c = -2.0f * (float)(gq + 8 * k);
        ck2[k] = pack2(c, c);
    }
    u64b jj = pack2(0.f, 1.f);
    const u64b two2 = pack2(2.f, 2.f);
    const float* Trow = &T[w * 66];

#pragma unroll 4
    for (int j = 0; j < 64; j += 2) {
        const u64b gg = *reinterpret_cast<const u64b*>(Trow + j);
#pragma unroll
        for (int k = 0; k < 8; k++) {
            const u64b c = fma2(ck2[k], jj, gg);
            acc[k] = fminf(acc[k], f2lo(c));
            acc[k] = fminf(acc[k], f2hi(c));
        }
        jj = add2(jj, two2);
    }
#pragma unroll
    for (int k = 0; k < 8; k++) {
        const int i = gq + 8 * k;
        g_F2[base + (size_t)i * 64 + w] = acc[k] + (float)(i * i);
    }
}

// ============================================================
// K3: EDT pass along D + sdf*prob reduction. Transposed padded
// tile + f32x2 j-pairs; IN tile staged via cp.async (raw) then
// transposed after the OUT loop.
// ============================================================
__global__ void __launch_bounds__(256, 4) k3_passD() {
    __shared__ __align__(16) float T[64 * 66];
    __shared__ __align__(16) float S[4096];
    __shared__ float red[8];
    const int p    = blockIdx.x >> 7;
    const int rem  = blockIdx.x & 127;
    const int h    = rem >> 1;
    const int half = rem & 1;
    const int tid = threadIdx.x;
    const int w = tid & 63;
    const int gq = tid >> 6;
    const int ib = half * 32 + gq;
    const size_t baseO = (size_t)(2 * p) * SVOL + (size_t)h * 64;
    const size_t baseI = baseO + SVOL;

    // ---- stage IN tile (raw float4) via cp.async ----
    const uint32_t sb = (uint32_t)__cvta_generic_to_shared(S);
#pragma unroll
    for (int r = 0; r < 4; r++) {
        int m = tid + r * 256;
        int dd = m >> 4;
        int w0 = (m & 15) * 4;
        cp_async16(sb + m * 16, &g_F2[baseI + (size_t)dd * 4096 + w0]);
    }
    asm volatile("cp.async.commit_group;");

    // ---- load OUT tile, fold +d^2, store transposed ----
#pragma unroll
    for (int r = 0; r < 4; r++) {
        int m = tid + r * 256;
        int dd = m >> 4;
        int w0 = (m & 15) * 4;
        float4 val = *reinterpret_cast<const float4*>(&g_F2[baseO + (size_t)dd * 4096 + w0]);
        float jv = (float)dd, j2 = jv * jv;
        T[(w0 + 0) * 66 + dd] = val.x + j2;
        T[(w0 + 1) * 66 + dd] = val.y + j2;
        T[(w0 + 2) * 66 + dd] = val.z + j2;
        T[(w0 + 3) * 66 + dd] = val.w + j2;
    }
    __syncthreads();

    u64b ck2[8];
#pragma unroll
    for (int k = 0; k < 8; k++) {
        float c = -2.0f * (float)(ib + 4 * k);
        ck2[k] = pack2(c, c);
    }
    const u64b two2 = pack2(2.f, 2.f);
    const float* Trow = &T[w * 66];

    float ro[8];
    {
        float acc[8];
#pragma unroll
        for (int k = 0; k < 8; k++) acc[k] = 3.0e38f;
        u64b jj = pack2(0.f, 1.f);
#pragma unroll 4
        for (int j = 0; j < 64; j += 2) {
            const u64b gg = *reinterpret_cast<const u64b*>(Trow + j);
#pragma unroll
            for (int k = 0; k < 8; k++) {
                const u64b c = fma2(ck2[k], jj, gg);
                acc[k] = fminf(acc[k], f2lo(c));
                acc[k] = fminf(acc[k], f2hi(c));
            }
            jj = add2(jj, two2);
        }
#pragma unroll
        for (int k = 0; k < 8; k++) {
            const int i = ib + 4 * k;
            ro[k] = acc[k] + (float)(i * i);
        }
    }

    // ---- transpose staged IN tile into T (own elements only) ----
    asm volatile("cp.async.wait_group 0;");
    __syncthreads();                    // everyone done reading T
#pragma unroll
    for (int r = 0; r < 4; r++) {
        int m = tid + r * 256;
        int dd = m >> 4;
        int w0 = (m & 15) * 4;
        float4 val = reinterpret_cast<const float4*>(S)[m];
        float jv = (float)dd, j2 = jv * jv;
        T[(w0 + 0) * 66 + dd] = val.x + j2;
        T[(w0 + 1) * 66 + dd] = val.y + j2;
        T[(w0 + 2) * 66 + dd] = val.z + j2;
        T[(w0 + 3) * 66 + dd] = val.w + j2;
    }
    __syncthreads();

    float local = 0.f;
    {
        float acc[8];
#pragma unroll
        for (int k = 0; k < 8; k++) acc[k] = 3.0e38f;
        u64b jj = pack2(0.f, 1.f);
#pragma unroll 4
        for (int j = 0; j < 64; j += 2) {
            const u64b gg = *reinterpret_cast<const u64b*>(Trow + j);
#pragma unroll
            for (int k = 0; k < 8; k++) {
                const u64b c = fma2(ck2[k], jj, gg);
                acc[k] = fminf(acc[k], f2lo(c));
                acc[k] = fminf(acc[k], f2hi(c));
            }
            jj = add2(jj, two2);
        }
#pragma unroll
        for (int k = 0; k < 8; k++) {
            const int i = ib + 4 * k;
            const float ri = acc[k] + (float)(i * i);
            const float sdf = sqrtf(ro[k]) - sqrtf(ri);
            const float pr = g_prob[(size_t)p * SVOL + (size_t)i * 4096 + (size_t)h * 64 + w];
            local = fmaf(sdf, pr, local);
        }
    }

#pragma unroll
    for (int o = 16; o > 0; o >>= 1) local += __shfl_down_sync(0xFFFFFFFFu, local, o);
    const int wid = tid >> 5;
    if ((tid & 31) == 0) red[wid] = local;
    __syncthreads();
    if (tid == 0) {
        float sum = 0.f;
#pragma unroll
        for (int k = 0; k < 8; k++) sum += red[k];
        atomicAdd(&g_bsum[p], sum);
    }
}

// ============================================================
// K4
// ============================================================
__global__ void k4_final(float* out) {
    if (threadIdx.x == 0) {
        float dice = 0.f;
        for (int bc = 0; bc < 16; bc++) {
            const float TP = g_TP[bc], PS = g_PS[bc], CNT = g_CNT[bc];
            const float FP = PS - TP;
            const float FN = CNT - TP;
            dice += (TP + SMOOTHV) / (TP + 0.3f * FP + 0.7f * FN + SMOOTHV);
        }
        const float l_dice = 1.0f - dice / 16.0f;
        const float l_main = g_focal / (float)NTOT;

        float bacc = 0.f;
        for (int p = 0; p < NPAIR; p++) {
            const int b = p / 3, c = p % 3 + 1;
            const float cnt = g_CNT[b * 4 + c];
            if (cnt > 0.f) {
                float contrib;
                if (cnt >= (float)SVOL)
                    contrib = -g_PS[b * 4 + c] / (float)SVOL;
                else
                    contrib = g_bsum[p] / (float)SVOL;
                bacc += contrib;
            }
        }
        const float l_bound = bacc / (12.0f + 1e-8f);
        out[0] = l_dice + l_main + 0.01f * l_bound;
    }
}

extern "C" void kernel_launch(void* const* d_in, const int* in_sizes, int n_in,
                              void* d_out, int out_size) {
    const float* preds = (const float*)d_in[0];
    const int*   tgt   = (const int*)d_in[1];
    (void)in_sizes; (void)n_in; (void)out_size;

    k0_init<<<1, 256>>>(tgt);
    k1_main<<<NTOT / 256, 256>>>(preds, tgt);
    k2_passH<<<NVOL * 64, 512>>>();
    k3_passD<<<NPAIR * 128, 256>>>();
    k4_final<<<1, 32>>>((float*)d_out);
}